// round 13
// baseline (speedup 1.0000x reference)
#include <cuda_runtime.h>
#include <cuda_fp16.h>
#include <math.h>
#include <stdint.h>

// ---------------------------------------------------------------- constants
#define BATCH   2
#define SEQ     2048
#define HID     1024
#define VOCAB_N 32000
#define ROWS    (BATCH * SEQ)     // 4096
#define QKV_N   (3 * HID)         // fused QKV output width

#define BM 128
#define BN 128
#define BK 32      // halves of K per stage (2 x k16 mma steps)
#define STRH 40    // smem row stride in halves; 80B stride -> LDSM phases conflict-free
#define GROUP_M 8  // CTA swizzle: m-tiles grouped for L2 reuse of B

// ---------------------------------------------------------------- scratch (fp16 pipeline)
__device__ __half g_h[ROWS * HID];
__device__ __half g_qkv[(size_t)ROWS * QKV_N];             // fused [ROWS, 3*HID]: q|k|v per row
__device__ __half g_attn[(size_t)BATCH * SEQ * SEQ];
__device__ __half g_z[ROWS * HID];
__device__ __half g_vT[(size_t)BATCH * HID * SEQ];         // v^T per batch [HID,SEQ]
__device__ __half g_wT[3 * (size_t)HID * HID + (size_t)HID * VOCAB_N]; // WqkvT | WoT

// ---------------------------------------------------------------- helpers
__device__ __forceinline__ void mma16(float* cc, const uint32_t* a,
                                      uint32_t b0, uint32_t b1) {
    asm volatile(
        "mma.sync.aligned.m16n8k16.row.col.f32.f16.f16.f32 "
        "{%0,%1,%2,%3}, {%4,%5,%6,%7}, {%8,%9}, {%0,%1,%2,%3};"
        : "+f"(cc[0]), "+f"(cc[1]), "+f"(cc[2]), "+f"(cc[3])
        : "r"(a[0]), "r"(a[1]), "r"(a[2]), "r"(a[3]), "r"(b0), "r"(b1));
}
__device__ __forceinline__ void ldsm4(uint32_t* r, uint32_t addr) {
    asm volatile("ldmatrix.sync.aligned.m8n8.x4.shared.b16 {%0,%1,%2,%3}, [%4];"
                 : "=r"(r[0]), "=r"(r[1]), "=r"(r[2]), "=r"(r[3]) : "r"(addr));
}

// ---------------------------------------------------------------- embedding -> fp16 h
__global__ void embed_kernel(const int* __restrict__ x,
                             const float* __restrict__ emb,
                             const float* __restrict__ pos) {
    int row = blockIdx.x;
    int s = row & (SEQ - 1);
    int tok = x[row];
    const float4* e  = (const float4*)(emb + (size_t)tok * HID);
    const float4* pe = (const float4*)(pos + (size_t)s * HID);
    __half2* o = (__half2*)(g_h + (size_t)row * HID);
    int t = threadIdx.x;
    float4 a = e[t], b = pe[t];
    o[2 * t]     = __floats2half2_rn(a.x + b.x, a.y + b.y);
    o[2 * t + 1] = __floats2half2_rn(a.z + b.z, a.w + b.w);
}

// ---------------------------------------------------------------- QKV weights convert+transpose
// z selects Wq/Wk/Wv; out row block z*HID gets W^T [HID(N), HID(K)]
__global__ void wT_qkv_kernel(const float* __restrict__ Wq,
                              const float* __restrict__ Wk,
                              const float* __restrict__ Wv,
                              __half* __restrict__ out) {
    __shared__ float t[32][33];
    const float* W = (blockIdx.z == 0) ? Wq : (blockIdx.z == 1) ? Wk : Wv;
    out += (size_t)blockIdx.z * HID * HID;
    int c0 = blockIdx.x * 32;   // N
    int r0 = blockIdx.y * 32;   // K
    int xx = threadIdx.x, yy = threadIdx.y;   // (32,8)
    #pragma unroll
    for (int i = 0; i < 32; i += 8)
        t[yy + i][xx] = W[(size_t)(r0 + yy + i) * HID + c0 + xx];
    __syncthreads();
    #pragma unroll
    for (int i = 0; i < 32; i += 8)
        out[(size_t)(c0 + yy + i) * HID + r0 + xx] = __float2half_rn(t[xx][yy + i]);
}

// generic f32 W [Kd, Nd] -> fp16 out [Nd, Kd]
__global__ void wT_kernel(const float* __restrict__ W, __half* __restrict__ out,
                          int Kd, int Nd) {
    __shared__ float t[32][33];
    int c0 = blockIdx.x * 32;
    int r0 = blockIdx.y * 32;
    int xx = threadIdx.x, yy = threadIdx.y;
    #pragma unroll
    for (int i = 0; i < 32; i += 8)
        t[yy + i][xx] = W[(size_t)(r0 + yy + i) * Nd + c0 + xx];
    __syncthreads();
    #pragma unroll
    for (int i = 0; i < 32; i += 8)
        out[(size_t)(c0 + yy + i) * Kd + r0 + xx] = __float2half_rn(t[xx][yy + i]);
}

// fp16 transpose with input ld: in [R, C-view] (row stride ldIn) -> out [C, R]
__global__ void hT_kernel(const __half* __restrict__ in, __half* __restrict__ out,
                          int R, int C, int ldIn, size_t sIn, size_t sOut) {
    __shared__ __half t[32][33];
    int zb = blockIdx.z;
    in += sIn * zb; out += sOut * zb;
    int c0 = blockIdx.x * 32, r0 = blockIdx.y * 32;
    int xx = threadIdx.x, yy = threadIdx.y;
    #pragma unroll
    for (int i = 0; i < 32; i += 8)
        t[yy + i][xx] = in[(size_t)(r0 + yy + i) * ldIn + c0 + xx];
    __syncthreads();
    #pragma unroll
    for (int i = 0; i < 32; i += 8)
        out[(size_t)(c0 + yy + i) * R + r0 + xx] = t[xx][yy + i];
}

// ---------------------------------------------------------------- fp16 mma GEMM (ldmatrix + swizzle)
// C[M,N] = A[M,K] * B^T   with A [M,K] fp16 row-major (lda), B [N,K] K-major (ldb).
template <int OUTF16>
__global__ void __launch_bounds__(256, 2)
hgemm(const __half* __restrict__ A, const __half* __restrict__ B,
      void* __restrict__ Cv, int K, int lda, int ldb, int ldc,
      const float* __restrict__ bias, const __half* __restrict__ residual,
      float scale, int causal_skip, int causal_klimit,
      size_t sA, size_t sB, size_t sC, size_t sR) {
    // --- CTA swizzle (gridDim.y divisible by GROUP_M) ---
    const int NT = gridDim.x;
    const int tile = blockIdx.y * NT + blockIdx.x;
    const int per = GROUP_M * NT;
    const int mi = (tile / per) * GROUP_M + (tile % per) % GROUP_M;
    const int ni = (tile % per) / GROUP_M;
    if (causal_skip && ni > mi) return;

    __shared__ __align__(16) __half As[2][BM * STRH];
    __shared__ __align__(16) __half Bs[2][BN * STRH];

    const int m0 = mi * BM;
    const int n0 = ni * BN;
    const int zb = blockIdx.z;
    A += sA * zb; B += sB * zb;
    if (residual) residual += sR * zb;

    const int kend = causal_klimit ? min(K, m0 + BM) : K;
    const int KT = kend / BK;

    const int tid  = threadIdx.x;
    const int lane = tid & 31;
    const int c = lane & 3;
    const int d = lane >> 2;
    const int wid = tid >> 5;
    const int wm = wid & 3;
    const int wn = wid >> 2;

    float acc[2][8][4];
    #pragma unroll
    for (int mt = 0; mt < 2; mt++)
        #pragma unroll
        for (int j = 0; j < 8; j++)
            #pragma unroll
            for (int t = 0; t < 4; t++) acc[mt][j][t] = 0.0f;

    const int lg = lane >> 3, lr = lane & 7;
    const uint32_t aSm = (uint32_t)__cvta_generic_to_shared(&As[0][0]);
    const uint32_t bSm = (uint32_t)__cvta_generic_to_shared(&Bs[0][0]);
    const uint32_t aBuf = BM * STRH * 2;
    const uint32_t bBuf = BN * STRH * 2;
    uint32_t aOff[2];
    #pragma unroll
    for (int mt = 0; mt < 2; mt++)
        aOff[mt] = ((wm * 32 + mt * 16 + (lg & 1) * 8 + lr) * STRH + (lg >> 1) * 8) * 2;
    uint32_t bOff[4];
    #pragma unroll
    for (int p = 0; p < 4; p++)
        bOff[p] = ((wn * 64 + p * 16 + (lg >> 1) * 8 + lr) * STRH + (lg & 1) * 8) * 2;

    uint4 pa[2], pb[2];
    auto ldg = [&](int k0) {
        #pragma unroll
        for (int i = 0; i < 2; i++) {
            int idx = tid + i * 256;
            int r = idx >> 2, ch = idx & 3;
            pa[i] = *(const uint4*)&A[(size_t)(m0 + r) * lda + k0 + ch * 8];
            pb[i] = *(const uint4*)&B[(size_t)(n0 + r) * ldb + k0 + ch * 8];
        }
    };
    auto sts = [&](int bf) {
        #pragma unroll
        for (int i = 0; i < 2; i++) {
            int idx = tid + i * 256;
            int r = idx >> 2, ch = idx & 3;
            *(uint4*)&As[bf][r * STRH + ch * 8] = pa[i];
            *(uint4*)&Bs[bf][r * STRH + ch * 8] = pb[i];
        }
    };

    ldg(0);
    sts(0);
    __syncthreads();
    if (1 < KT) ldg(BK);

    for (int kt = 0; kt < KT; kt++) {
        const int cur = kt & 1;
        const uint32_t aC = aSm + cur * aBuf;
        const uint32_t bC = bSm + cur * bBuf;

        #pragma unroll
        for (int s = 0; s < 2; s++) {
            const uint32_t so = s * 32;
            uint32_t a[2][4];
            ldsm4(a[0], aC + aOff[0] + so);
            ldsm4(a[1], aC + aOff[1] + so);
            uint32_t bf[16];
            ldsm4(bf +  0, bC + bOff[0] + so);
            ldsm4(bf +  4, bC + bOff[1] + so);
            ldsm4(bf +  8, bC + bOff[2] + so);
            ldsm4(bf + 12, bC + bOff[3] + so);
            #pragma unroll
            for (int j = 0; j < 8; j++) {
                mma16(acc[0][j], a[0], bf[2 * j], bf[2 * j + 1]);
                mma16(acc[1][j], a[1], bf[2 * j], bf[2 * j + 1]);
            }
        }

        if (kt + 1 < KT) {
            sts(cur ^ 1);
            __syncthreads();
            if (kt + 2 < KT) ldg((kt + 2) * BK);
        }
    }

    // ---- epilogue
    #pragma unroll
    for (int mt = 0; mt < 2; mt++) {
        int row0 = m0 + wm * 32 + mt * 16 + d;
        #pragma unroll
        for (int j = 0; j < 8; j++) {
            int col = n0 + wn * 64 + j * 8 + 2 * c;
            float bx = 0.0f, by = 0.0f;
            if (bias) { bx = bias[col]; by = bias[col + 1]; }
            #pragma unroll
            for (int hrow = 0; hrow < 2; hrow++) {
                int rr = row0 + hrow * 8;
                size_t o = (size_t)rr * ldc + col;
                float vx = acc[mt][j][2 * hrow + 0] * scale + bx;
                float vy = acc[mt][j][2 * hrow + 1] * scale + by;
                if (residual) {
                    float2 rv = __half22float2(*(const __half2*)&residual[o]);
                    vx += rv.x; vy += rv.y;
                }
                if (OUTF16) {
                    *(__half2*)&((__half*)Cv + sC * zb)[o] = __floats2half2_rn(vx, vy);
                } else {
                    *(float2*)&((float*)Cv + sC * zb)[o] = make_float2(vx, vy);
                }
            }
        }
    }
}

// ---------------------------------------------------------------- softmax (fp16 in/out)
__global__ void softmax_causal_kernel() {
    int row = blockIdx.x;
    int s = row & (SEQ - 1);
    __half* p = g_attn + (size_t)row * SEQ;
    int L = s + 1;
    __shared__ float red[256];
    int tid = threadIdx.x;

    float m = -1e30f;
    for (int t = tid; t < L; t += 256) m = fmaxf(m, __half2float(p[t]));
    red[tid] = m; __syncthreads();
    #pragma unroll
    for (int o = 128; o > 0; o >>= 1) {
        if (tid < o) red[tid] = fmaxf(red[tid], red[tid + o]);
        __syncthreads();
    }
    m = red[0]; __syncthreads();

    float sum = 0.0f;
    for (int t = tid; t < L; t += 256) sum += __expf(__half2float(p[t]) - m);
    red[tid] = sum; __syncthreads();
    #pragma unroll
    for (int o = 128; o > 0; o >>= 1) {
        if (tid < o) red[tid] += red[tid + o];
        __syncthreads();
    }
    float inv = 1.0f / red[0];

    for (int t = tid; t < L; t += 256)
        p[t] = __float2half_rn(__expf(__half2float(p[t]) - m) * inv);
    for (int t = L + tid; t < SEQ; t += 256) p[t] = __float2half_rn(0.0f);
}

// ---------------------------------------------------------------- launch
extern "C" void kernel_launch(void* const* d_in, const int* in_sizes, int n_in,
                              void* d_out, int out_size) {
    const int*   x    = (const int*)  d_in[0];
    const float* emb  = (const float*)d_in[1];
    const float* pos  = (const float*)d_in[2];
    const float* Wk   = (const float*)d_in[3];
    const float* Wq   = (const float*)d_in[4];
    const float* Wv   = (const float*)d_in[5];
    const float* Wo   = (const float*)d_in[6];
    const float* bo   = (const float*)d_in[7];
    float* out = (float*)d_out;

    static __half *h = nullptr, *qkv, *attn, *z, *vT, *wT;
    if (!h) {
        cudaGetSymbolAddress((void**)&h,    g_h);
        cudaGetSymbolAddress((void**)&qkv,  g_qkv);
        cudaGetSymbolAddress((void**)&attn, g_attn);
        cudaGetSymbolAddress((void**)&z,    g_z);
        cudaGetSymbolAddress((void**)&vT,   g_vT);
        cudaGetSymbolAddress((void**)&wT,   g_wT);
    }
    const size_t SH = (size_t)SEQ * HID;
    const size_t SS = (size_t)SEQ * SEQ;
    const size_t HH = (size_t)HID * HID;

    __half* WqkvT = wT;              // [3072, 1024] K-major
    __half* WoT   = wT + 3 * HH;     // [32000, 1024] K-major

    // Fused-QKV views: row stride QKV_N
    __half* q = qkv;
    __half* k = qkv + HID;
    __half* v = qkv + 2 * HID;

    dim3 tb(32, 8);

    // L1: embedding -> fp16 h
    embed_kernel<<<ROWS, 256>>>(x, emb, pos);

    // L2: Wq|Wk|Wv -> packed K-major fp16 (one launch, z=3)
    wT_qkv_kernel<<<dim3(HID / 32, HID / 32, 3), tb>>>(Wq, Wk, Wv, WqkvT);

    // L3: fused QKV gemm: [4096,1024] x [3072,1024]^T -> [4096,3072]
    {
        dim3 grid(QKV_N / BN, ROWS / BM, 1);
        hgemm<1><<<grid, 256>>>(h, WqkvT, qkv, HID, HID, HID, QKV_N,
            nullptr, nullptr, 1.0f, 0, 0, 0, 0, 0, 0);
    }

    // L4 (captured by ncu): scores = q k^T / 32, causal blocks only
    {
        dim3 grid(SEQ / BN, SEQ / BM, BATCH);
        hgemm<1><<<grid, 256>>>(q, k, attn, HID, QKV_N, QKV_N, SEQ,
            nullptr, nullptr, 1.0f / 32.0f, 1, 0,
            SEQ * (size_t)QKV_N, SEQ * (size_t)QKV_N, SS, 0);
    }

    // L5: causal softmax in place
    softmax_causal_kernel<<<ROWS, 256>>>();

    // L6: v^T per batch: view [SEQ,HID] (ld QKV_N) -> [HID,SEQ]
    hT_kernel<<<dim3(HID / 32, SEQ / 32, BATCH), tb>>>(
        v, vT, SEQ, HID, QKV_N, SEQ * (size_t)QKV_N, SH);

    // L7: z = attn @ v + h  (K causally limited)
    {
        dim3 grid(HID / BN, SEQ / BM, BATCH);
        hgemm<1><<<grid, 256>>>(attn, vT, z, SEQ, SEQ, SEQ, HID,
            nullptr, h, 1.0f, 0, 1, SS, SH, SH, SH);
    }

    // L8: Wo -> K-major fp16
    wT_kernel<<<dim3(VOCAB_N / 32, HID / 32), tb>>>(Wo, WoT, HID, VOCAB_N);

    // L9: out = z @ Wo + bo (f32 out)
    {
        dim3 grid(VOCAB_N / BN, ROWS / BM, 1);
        hgemm<0><<<grid, 256>>>(z, WoT, out, HID, HID, HID, VOCAB_N,
            bo, nullptr, 1.0f, 0, 0, 0, 0, 0, 0);
    }
}

// round 14
// speedup vs baseline: 1.0030x; 1.0030x over previous
#include <cuda_runtime.h>
#include <cuda_fp16.h>
#include <math.h>
#include <stdint.h>

// ---------------------------------------------------------------- constants
#define BATCH   2
#define SEQ     2048
#define HID     1024
#define VOCAB_N 32000
#define ROWS    (BATCH * SEQ)     // 4096
#define QKV_N   (3 * HID)

#define BM 128
#define BN 256
#define BK 32      // halves of K per stage (2 x k16 mma steps)
#define STRH 40    // smem row stride in halves; 80B stride -> LDSM conflict-free
#define GROUP_M 8

#define A_BUF_H (BM * STRH)             // halves per A buffer
#define B_BUF_H (BN * STRH)
#define SMEM_BYTES ((2 * A_BUF_H + 2 * B_BUF_H) * 2)   // 61440

// ---------------------------------------------------------------- scratch (fp16 pipeline)
__device__ __half g_h[ROWS * HID];
__device__ __half g_qkv[(size_t)ROWS * QKV_N];             // fused [ROWS, 3*HID]
__device__ __half g_attn[(size_t)BATCH * SEQ * SEQ];
__device__ __half g_z[ROWS * HID];
__device__ __half g_vT[(size_t)BATCH * HID * SEQ];
__device__ __half g_wT[3 * (size_t)HID * HID + (size_t)HID * VOCAB_N]; // WqkvT | WoT

// ---------------------------------------------------------------- helpers
__device__ __forceinline__ void mma16(float* cc, const uint32_t* a,
                                      uint32_t b0, uint32_t b1) {
    asm volatile(
        "mma.sync.aligned.m16n8k16.row.col.f32.f16.f16.f32 "
        "{%0,%1,%2,%3}, {%4,%5,%6,%7}, {%8,%9}, {%0,%1,%2,%3};"
        : "+f"(cc[0]), "+f"(cc[1]), "+f"(cc[2]), "+f"(cc[3])
        : "r"(a[0]), "r"(a[1]), "r"(a[2]), "r"(a[3]), "r"(b0), "r"(b1));
}
__device__ __forceinline__ void ldsm4(uint32_t* r, uint32_t addr) {
    asm volatile("ldmatrix.sync.aligned.m8n8.x4.shared.b16 {%0,%1,%2,%3}, [%4];"
                 : "=r"(r[0]), "=r"(r[1]), "=r"(r[2]), "=r"(r[3]) : "r"(addr));
}

// ---------------------------------------------------------------- embedding -> fp16 h
__global__ void embed_kernel(const int* __restrict__ x,
                             const float* __restrict__ emb,
                             const float* __restrict__ pos) {
    int row = blockIdx.x;
    int s = row & (SEQ - 1);
    int tok = x[row];
    const float4* e  = (const float4*)(emb + (size_t)tok * HID);
    const float4* pe = (const float4*)(pos + (size_t)s * HID);
    __half2* o = (__half2*)(g_h + (size_t)row * HID);
    int t = threadIdx.x;
    float4 a = e[t], b = pe[t];
    o[2 * t]     = __floats2half2_rn(a.x + b.x, a.y + b.y);
    o[2 * t + 1] = __floats2half2_rn(a.z + b.z, a.w + b.w);
}

// ---------------------------------------------------------------- weight transposes
__global__ void wT_qkv_kernel(const float* __restrict__ Wq,
                              const float* __restrict__ Wk,
                              const float* __restrict__ Wv,
                              __half* __restrict__ out) {
    __shared__ float t[32][33];
    const float* W = (blockIdx.z == 0) ? Wq : (blockIdx.z == 1) ? Wk : Wv;
    out += (size_t)blockIdx.z * HID * HID;
    int c0 = blockIdx.x * 32;
    int r0 = blockIdx.y * 32;
    int xx = threadIdx.x, yy = threadIdx.y;
    #pragma unroll
    for (int i = 0; i < 32; i += 8)
        t[yy + i][xx] = W[(size_t)(r0 + yy + i) * HID + c0 + xx];
    __syncthreads();
    #pragma unroll
    for (int i = 0; i < 32; i += 8)
        out[(size_t)(c0 + yy + i) * HID + r0 + xx] = __float2half_rn(t[xx][yy + i]);
}

__global__ void wT_kernel(const float* __restrict__ W, __half* __restrict__ out,
                          int Kd, int Nd) {
    __shared__ float t[32][33];
    int c0 = blockIdx.x * 32;
    int r0 = blockIdx.y * 32;
    int xx = threadIdx.x, yy = threadIdx.y;
    #pragma unroll
    for (int i = 0; i < 32; i += 8)
        t[yy + i][xx] = W[(size_t)(r0 + yy + i) * Nd + c0 + xx];
    __syncthreads();
    #pragma unroll
    for (int i = 0; i < 32; i += 8)
        out[(size_t)(c0 + yy + i) * Kd + r0 + xx] = __float2half_rn(t[xx][yy + i]);
}

__global__ void hT_kernel(const __half* __restrict__ in, __half* __restrict__ out,
                          int R, int C, int ldIn, size_t sIn, size_t sOut) {
    __shared__ __half t[32][33];
    int zb = blockIdx.z;
    in += sIn * zb; out += sOut * zb;
    int c0 = blockIdx.x * 32, r0 = blockIdx.y * 32;
    int xx = threadIdx.x, yy = threadIdx.y;
    #pragma unroll
    for (int i = 0; i < 32; i += 8)
        t[yy + i][xx] = in[(size_t)(r0 + yy + i) * ldIn + c0 + xx];
    __syncthreads();
    #pragma unroll
    for (int i = 0; i < 32; i += 8)
        out[(size_t)(c0 + yy + i) * R + r0 + xx] = t[xx][yy + i];
}

// ---------------------------------------------------------------- fp16 mma GEMM
// BM=128 x BN=256, 8 warps as 2m x 4n (warp tile 64x64).
// C[M,N] = A[M,K] * B^T   A [M,K] row-major (lda), B [N,K] K-major (ldb).
template <int OUTF16>
__global__ void __launch_bounds__(256, 1)
hgemm(const __half* __restrict__ A, const __half* __restrict__ B,
      void* __restrict__ Cv, int K, int lda, int ldb, int ldc,
      const float* __restrict__ bias, const __half* __restrict__ residual,
      float scale, int causal_skip, int causal_klimit,
      size_t sA, size_t sB, size_t sC, size_t sR) {
    // --- CTA swizzle ---
    const int NT = gridDim.x;
    const int tile = blockIdx.y * NT + blockIdx.x;
    const int per = GROUP_M * NT;
    const int mi = (tile / per) * GROUP_M + (tile % per) % GROUP_M;
    const int ni = (tile % per) / GROUP_M;
    const int m0 = mi * BM;
    const int n0 = ni * BN;
    if (causal_skip && n0 > m0 + BM - 1) return;

    extern __shared__ __half smh[];
    __half* Abuf = smh;                        // 2 x A_BUF_H
    __half* Bbuf = smh + 2 * A_BUF_H;          // 2 x B_BUF_H

    const int zb = blockIdx.z;
    A += sA * zb; B += sB * zb;
    if (residual) residual += sR * zb;

    const int kend = causal_klimit ? min(K, m0 + BM) : K;
    const int KT = kend / BK;

    const int tid  = threadIdx.x;
    const int lane = tid & 31;
    const int c = lane & 3;
    const int d = lane >> 2;
    const int wid = tid >> 5;
    const int wm = wid & 1;        // warp m (0..1): rows wm*64..+63
    const int wn = wid >> 1;       // warp n (0..3): cols wn*64..+63

    float acc[4][8][4];
    #pragma unroll
    for (int mt = 0; mt < 4; mt++)
        #pragma unroll
        for (int j = 0; j < 8; j++)
            #pragma unroll
            for (int t = 0; t < 4; t++) acc[mt][j][t] = 0.0f;

    const int lg = lane >> 3, lr = lane & 7;
    const uint32_t aSm = (uint32_t)__cvta_generic_to_shared(Abuf);
    const uint32_t bSm = (uint32_t)__cvta_generic_to_shared(Bbuf);
    const uint32_t aBufB = A_BUF_H * 2;
    const uint32_t bBufB = B_BUF_H * 2;
    uint32_t aOff[4];
    #pragma unroll
    for (int mt = 0; mt < 4; mt++)
        aOff[mt] = ((wm * 64 + mt * 16 + (lg & 1) * 8 + lr) * STRH + (lg >> 1) * 8) * 2;
    uint32_t bOff[4];
    #pragma unroll
    for (int p = 0; p < 4; p++)
        bOff[p] = ((wn * 64 + p * 16 + (lg >> 1) * 8 + lr) * STRH + (lg & 1) * 8) * 2;

    uint4 pa[2], pb[4];
    // A: 128 rows x 4 chunks(16B) = 512; B: 256 x 4 = 1024; over 256 threads
    auto ldg = [&](int k0) {
        #pragma unroll
        for (int i = 0; i < 2; i++) {
            int idx = tid + i * 256;
            int r = idx >> 2, ch = idx & 3;
            pa[i] = *(const uint4*)&A[(size_t)(m0 + r) * lda + k0 + ch * 8];
        }
        #pragma unroll
        for (int i = 0; i < 4; i++) {
            int idx = tid + i * 256;
            int r = idx >> 2, ch = idx & 3;
            pb[i] = *(const uint4*)&B[(size_t)(n0 + r) * ldb + k0 + ch * 8];
        }
    };
    auto sts = [&](int bf) {
        #pragma unroll
        for (int i = 0; i < 2; i++) {
            int idx = tid + i * 256;
            int r = idx >> 2, ch = idx & 3;
            *(uint4*)&Abuf[bf * A_BUF_H + r * STRH + ch * 8] = pa[i];
        }
        #pragma unroll
        for (int i = 0; i < 4; i++) {
            int idx = tid + i * 256;
            int r = idx >> 2, ch = idx & 3;
            *(uint4*)&Bbuf[bf * B_BUF_H + r * STRH + ch * 8] = pb[i];
        }
    };

    ldg(0);
    sts(0);
    __syncthreads();
    if (1 < KT) ldg(BK);

    for (int kt = 0; kt < KT; kt++) {
        const int cur = kt & 1;
        const uint32_t aC = aSm + cur * aBufB;
        const uint32_t bC = bSm + cur * bBufB;

        #pragma unroll
        for (int s = 0; s < 2; s++) {
            const uint32_t so = s * 32;
            uint32_t a[4][4];
            ldsm4(a[0], aC + aOff[0] + so);
            ldsm4(a[1], aC + aOff[1] + so);
            ldsm4(a[2], aC + aOff[2] + so);
            ldsm4(a[3], aC + aOff[3] + so);
            uint32_t bf[16];
            ldsm4(bf +  0, bC + bOff[0] + so);
            ldsm4(bf +  4, bC + bOff[1] + so);
            ldsm4(bf +  8, bC + bOff[2] + so);
            ldsm4(bf + 12, bC + bOff[3] + so);
            #pragma unroll
            for (int mt = 0; mt < 4; mt++)
                #pragma unroll
                for (int j = 0; j < 8; j++)
                    mma16(acc[mt][j], a[mt], bf[2 * j], bf[2 * j + 1]);
        }

        if (kt + 1 < KT) {
            sts(cur ^ 1);
            __syncthreads();
            if (kt + 2 < KT) ldg((kt + 2) * BK);
        }
    }

    // ---- epilogue
    #pragma unroll
    for (int mt = 0; mt < 4; mt++) {
        int row0 = m0 + wm * 64 + mt * 16 + d;
        #pragma unroll
        for (int j = 0; j < 8; j++) {
            int col = n0 + wn * 64 + j * 8 + 2 * c;
            float bx = 0.0f, by = 0.0f;
            if (bias) { bx = bias[col]; by = bias[col + 1]; }
            #pragma unroll
            for (int hrow = 0; hrow < 2; hrow++) {
                int rr = row0 + hrow * 8;
                size_t o = (size_t)rr * ldc + col;
                float vx = acc[mt][j][2 * hrow + 0] * scale + bx;
                float vy = acc[mt][j][2 * hrow + 1] * scale + by;
                if (residual) {
                    float2 rv = __half22float2(*(const __half2*)&residual[o]);
                    vx += rv.x; vy += rv.y;
                }
                if (OUTF16) {
                    *(__half2*)&((__half*)Cv + sC * zb)[o] = __floats2half2_rn(vx, vy);
                } else {
                    *(float2*)&((float*)Cv + sC * zb)[o] = make_float2(vx, vy);
                }
            }
        }
    }
}

// ---------------------------------------------------------------- softmax (fp16 in/out)
__global__ void softmax_causal_kernel() {
    int row = blockIdx.x;
    int s = row & (SEQ - 1);
    __half* p = g_attn + (size_t)row * SEQ;
    int L = s + 1;
    __shared__ float red[256];
    int tid = threadIdx.x;

    float m = -1e30f;
    for (int t = tid; t < L; t += 256) m = fmaxf(m, __half2float(p[t]));
    red[tid] = m; __syncthreads();
    #pragma unroll
    for (int o = 128; o > 0; o >>= 1) {
        if (tid < o) red[tid] = fmaxf(red[tid], red[tid + o]);
        __syncthreads();
    }
    m = red[0]; __syncthreads();

    float sum = 0.0f;
    for (int t = tid; t < L; t += 256) sum += __expf(__half2float(p[t]) - m);
    red[tid] = sum; __syncthreads();
    #pragma unroll
    for (int o = 128; o > 0; o >>= 1) {
        if (tid < o) red[tid] += red[tid + o];
        __syncthreads();
    }
    float inv = 1.0f / red[0];

    for (int t = tid; t < L; t += 256)
        p[t] = __float2half_rn(__expf(__half2float(p[t]) - m) * inv);
    for (int t = L + tid; t < SEQ; t += 256) p[t] = __float2half_rn(0.0f);
}

// ---------------------------------------------------------------- launch
extern "C" void kernel_launch(void* const* d_in, const int* in_sizes, int n_in,
                              void* d_out, int out_size) {
    const int*   x    = (const int*)  d_in[0];
    const float* emb  = (const float*)d_in[1];
    const float* pos  = (const float*)d_in[2];
    const float* Wk   = (const float*)d_in[3];
    const float* Wq   = (const float*)d_in[4];
    const float* Wv   = (const float*)d_in[5];
    const float* Wo   = (const float*)d_in[6];
    const float* bo   = (const float*)d_in[7];
    float* out = (float*)d_out;

    static __half *h = nullptr, *qkv, *attn, *z, *vT, *wT;
    if (!h) {
        cudaGetSymbolAddress((void**)&h,    g_h);
        cudaGetSymbolAddress((void**)&qkv,  g_qkv);
        cudaGetSymbolAddress((void**)&attn, g_attn);
        cudaGetSymbolAddress((void**)&z,    g_z);
        cudaGetSymbolAddress((void**)&vT,   g_vT);
        cudaGetSymbolAddress((void**)&wT,   g_wT);
        cudaFuncSetAttribute(hgemm<0>,
            cudaFuncAttributeMaxDynamicSharedMemorySize, SMEM_BYTES);
        cudaFuncSetAttribute(hgemm<1>,
            cudaFuncAttributeMaxDynamicSharedMemorySize, SMEM_BYTES);
    }
    const size_t SH = (size_t)SEQ * HID;
    const size_t SS = (size_t)SEQ * SEQ;
    const size_t HH = (size_t)HID * HID;

    __half* WqkvT = wT;
    __half* WoT   = wT + 3 * HH;

    __half* q = qkv;
    __half* k = qkv + HID;
    __half* v = qkv + 2 * HID;

    dim3 tb(32, 8);

    // L1: embedding
    embed_kernel<<<ROWS, 256>>>(x, emb, pos);

    // L2: Wq|Wk|Wv -> packed K-major fp16
    wT_qkv_kernel<<<dim3(HID / 32, HID / 32, 3), tb>>>(Wq, Wk, Wv, WqkvT);

    // L3: fused QKV gemm
    {
        dim3 grid(QKV_N / BN, ROWS / BM, 1);
        hgemm<1><<<grid, 256, SMEM_BYTES>>>(h, WqkvT, qkv, HID, HID, HID, QKV_N,
            nullptr, nullptr, 1.0f, 0, 0, 0, 0, 0, 0);
    }

    // L4 (captured): scores = q k^T / 32
    {
        dim3 grid(SEQ / BN, SEQ / BM, BATCH);
        hgemm<1><<<grid, 256, SMEM_BYTES>>>(q, k, attn, HID, QKV_N, QKV_N, SEQ,
            nullptr, nullptr, 1.0f / 32.0f, 1, 0,
            SEQ * (size_t)QKV_N, SEQ * (size_t)QKV_N, SS, 0);
    }

    // L5: softmax
    softmax_causal_kernel<<<ROWS, 256>>>();

    // L6: v^T per batch
    hT_kernel<<<dim3(HID / 32, SEQ / 32, BATCH), tb>>>(
        v, vT, SEQ, HID, QKV_N, SEQ * (size_t)QKV_N, SH);

    // L7: z = attn @ v + h
    {
        dim3 grid(HID / BN, SEQ / BM, BATCH);
        hgemm<1><<<grid, 256, SMEM_BYTES>>>(attn, vT, z, SEQ, SEQ, SEQ, HID,
            nullptr, h, 1.0f, 0, 1, SS, SH, SH, SH);
    }

    // L8: Wo -> K-major fp16
    wT_kernel<<<dim3(VOCAB_N / 32, HID / 32), tb>>>(Wo, WoT, HID, VOCAB_N);

    // L9: out = z @ Wo + bo (f32)
    {
        dim3 grid(VOCAB_N / BN, ROWS / BM, 1);
        hgemm<0><<<grid, 256, SMEM_BYTES>>>(z, WoT, out, HID, HID, HID, VOCAB_N,
            bo, nullptr, 1.0f, 0, 0, 0, 0, 0, 0);
    }
}

// round 17
// speedup vs baseline: 1.0997x; 1.0965x over previous
#include <cuda_runtime.h>
#include <cuda_fp16.h>
#include <math.h>
#include <stdint.h>

// ---------------------------------------------------------------- constants
#define BATCH   2
#define SEQ     2048
#define HID     1024
#define VOCAB_N 32000
#define ROWS    (BATCH * SEQ)     // 4096
#define QKV_N   (3 * HID)

#define BM 128
#define BN 128
#define BK 32      // halves of K per stage (2 x k16 mma steps)
#define STRH 40    // smem row stride in halves; 80B stride -> LDSM conflict-free
#define GROUP_M 8
#define NTHREADS 128

#define A_BUF_H (BM * STRH)
#define B_BUF_H (BN * STRH)
#define SMEM_BYTES ((2 * A_BUF_H + 2 * B_BUF_H) * 2)   // 40960

// ---------------------------------------------------------------- scratch (fp16 pipeline)
__device__ __half g_h[ROWS * HID];
__device__ __half g_qkv[(size_t)ROWS * QKV_N];             // fused [ROWS, 3*HID]
__device__ __half g_attn[(size_t)BATCH * SEQ * SEQ];
__device__ __half g_z[ROWS * HID];
__device__ __half g_vT[(size_t)BATCH * HID * SEQ];
__device__ __half g_wT[3 * (size_t)HID * HID + (size_t)HID * VOCAB_N]; // WqkvT | WoT

// ---------------------------------------------------------------- helpers
__device__ __forceinline__ void mma16(float* cc, const uint32_t* a,
                                      uint32_t b0, uint32_t b1) {
    asm volatile(
        "mma.sync.aligned.m16n8k16.row.col.f32.f16.f16.f32 "
        "{%0,%1,%2,%3}, {%4,%5,%6,%7}, {%8,%9}, {%0,%1,%2,%3};"
        : "+f"(cc[0]), "+f"(cc[1]), "+f"(cc[2]), "+f"(cc[3])
        : "r"(a[0]), "r"(a[1]), "r"(a[2]), "r"(a[3]), "r"(b0), "r"(b1));
}
__device__ __forceinline__ void ldsm4(uint32_t* r, uint32_t addr) {
    asm volatile("ldmatrix.sync.aligned.m8n8.x4.shared.b16 {%0,%1,%2,%3}, [%4];"
                 : "=r"(r[0]), "=r"(r[1]), "=r"(r[2]), "=r"(r[3]) : "r"(addr));
}

// ---------------------------------------------------------------- embedding -> fp16 h
__global__ void embed_kernel(const int* __restrict__ x,
                             const float* __restrict__ emb,
                             const float* __restrict__ pos) {
    int row = blockIdx.x;
    int s = row & (SEQ - 1);
    int tok = x[row];
    const float4* e  = (const float4*)(emb + (size_t)tok * HID);
    const float4* pe = (const float4*)(pos + (size_t)s * HID);
    __half2* o = (__half2*)(g_h + (size_t)row * HID);
    int t = threadIdx.x;
    float4 a = e[t], b = pe[t];
    o[2 * t]     = __floats2half2_rn(a.x + b.x, a.y + b.y);
    o[2 * t + 1] = __floats2half2_rn(a.z + b.z, a.w + b.w);
}

// ---------------------------------------------------------------- weight transposes
__global__ void wT_qkv_kernel(const float* __restrict__ Wq,
                              const float* __restrict__ Wk,
                              const float* __restrict__ Wv,
                              __half* __restrict__ out) {
    __shared__ float t[32][33];
    const float* W = (blockIdx.z == 0) ? Wq : (blockIdx.z == 1) ? Wk : Wv;
    out += (size_t)blockIdx.z * HID * HID;
    int c0 = blockIdx.x * 32;
    int r0 = blockIdx.y * 32;
    int xx = threadIdx.x, yy = threadIdx.y;
    #pragma unroll
    for (int i = 0; i < 32; i += 8)
        t[yy + i][xx] = W[(size_t)(r0 + yy + i) * HID + c0 + xx];
    __syncthreads();
    #pragma unroll
    for (int i = 0; i < 32; i += 8)
        out[(size_t)(c0 + yy + i) * HID + r0 + xx] = __float2half_rn(t[xx][yy + i]);
}

__global__ void wT_kernel(const float* __restrict__ W, __half* __restrict__ out,
                          int Kd, int Nd) {
    __shared__ float t[32][33];
    int c0 = blockIdx.x * 32;
    int r0 = blockIdx.y * 32;
    int xx = threadIdx.x, yy = threadIdx.y;
    #pragma unroll
    for (int i = 0; i < 32; i += 8)
        t[yy + i][xx] = W[(size_t)(r0 + yy + i) * Nd + c0 + xx];
    __syncthreads();
    #pragma unroll
    for (int i = 0; i < 32; i += 8)
        out[(size_t)(c0 + yy + i) * Kd + r0 + xx] = __float2half_rn(t[xx][yy + i]);
}

__global__ void hT_kernel(const __half* __restrict__ in, __half* __restrict__ out,
                          int R, int C, int ldIn, size_t sIn, size_t sOut) {
    __shared__ __half t[32][33];
    int zb = blockIdx.z;
    in += sIn * zb; out += sOut * zb;
    int c0 = blockIdx.x * 32, r0 = blockIdx.y * 32;
    int xx = threadIdx.x, yy = threadIdx.y;
    #pragma unroll
    for (int i = 0; i < 32; i += 8)
        t[yy + i][xx] = in[(size_t)(r0 + yy + i) * ldIn + c0 + xx];
    __syncthreads();
    #pragma unroll
    for (int i = 0; i < 32; i += 8)
        out[(size_t)(c0 + yy + i) * R + r0 + xx] = t[xx][yy + i];
}

// ---------------------------------------------------------------- fp16 mma GEMM
// BM=128 x BN=128, 4 warps as 2m x 2n (warp tile 64x64), 2 CTAs/SM.
// C[M,N] = A[M,K] * B^T   A [M,K] row-major (lda), B [N,K] K-major (ldb).
template <int OUTF16>
__global__ void __launch_bounds__(NTHREADS, 2)
hgemm(const __half* __restrict__ A, const __half* __restrict__ B,
      void* __restrict__ Cv, int K, int lda, int ldb, int ldc,
      const float* __restrict__ bias, const __half* __restrict__ residual,
      float scale, int causal_skip, int causal_klimit,
      size_t sA, size_t sB, size_t sC, size_t sR) {
    // --- CTA swizzle ---
    const int NT = gridDim.x;
    const int tile = blockIdx.y * NT + blockIdx.x;
    const int per = GROUP_M * NT;
    const int mi = (tile / per) * GROUP_M + (tile % per) % GROUP_M;
    const int ni = (tile % per) / GROUP_M;
    const int m0 = mi * BM;
    const int n0 = ni * BN;
    if (causal_skip && n0 > m0 + BM - 1) return;

    extern __shared__ __half smh[];
    __half* Abuf = smh;                        // 2 x A_BUF_H
    __half* Bbuf = smh + 2 * A_BUF_H;          // 2 x B_BUF_H

    const int zb = blockIdx.z;
    A += sA * zb; B += sB * zb;
    if (residual) residual += sR * zb;

    const int kend = causal_klimit ? min(K, m0 + BM) : K;
    const int KT = kend / BK;

    const int tid  = threadIdx.x;
    const int lane = tid & 31;
    const int c = lane & 3;
    const int d = lane >> 2;
    const int wid = tid >> 5;
    const int wm = wid & 1;        // warp m (0..1): rows wm*64..+63
    const int wn = wid >> 1;       // warp n (0..1): cols wn*64..+63

    float acc[4][8][4];
    #pragma unroll
    for (int mt = 0; mt < 4; mt++)
        #pragma unroll
        for (int j = 0; j < 8; j++)
            #pragma unroll
            for (int t = 0; t < 4; t++) acc[mt][j][t] = 0.0f;

    const int lg = lane >> 3, lr = lane & 7;
    const uint32_t aSm = (uint32_t)__cvta_generic_to_shared(Abuf);
    const uint32_t bSm = (uint32_t)__cvta_generic_to_shared(Bbuf);
    const uint32_t aBufB = A_BUF_H * 2;
    const uint32_t bBufB = B_BUF_H * 2;
    uint32_t aOff[4];
    #pragma unroll
    for (int mt = 0; mt < 4; mt++)
        aOff[mt] = ((wm * 64 + mt * 16 + (lg & 1) * 8 + lr) * STRH + (lg >> 1) * 8) * 2;
    uint32_t bOff[4];
    #pragma unroll
    for (int p = 0; p < 4; p++)
        bOff[p] = ((wn * 64 + p * 16 + (lg >> 1) * 8 + lr) * STRH + (lg & 1) * 8) * 2;

    uint4 pa[4], pb[4];
    // A: 128 rows x 4 chunks(16B) = 512 over 128 threads -> 4 each; B same
    auto ldg = [&](int k0) {
        #pragma unroll
        for (int i = 0; i < 4; i++) {
            int idx = tid + i * NTHREADS;
            int r = idx >> 2, ch = idx & 3;
            pa[i] = *(const uint4*)&A[(size_t)(m0 + r) * lda + k0 + ch * 8];
            pb[i] = *(const uint4*)&B[(size_t)(n0 + r) * ldb + k0 + ch * 8];
        }
    };
    auto sts = [&](int bf) {
        #pragma unroll
        for (int i = 0; i < 4; i++) {
            int idx = tid + i * NTHREADS;
            int r = idx >> 2, ch = idx & 3;
            *(uint4*)&Abuf[bf * A_BUF_H + r * STRH + ch * 8] = pa[i];
            *(uint4*)&Bbuf[bf * B_BUF_H + r * STRH + ch * 8] = pb[i];
        }
    };

    ldg(0);
    sts(0);
    __syncthreads();
    if (1 < KT) ldg(BK);

    for (int kt = 0; kt < KT; kt++) {
        const int cur = kt & 1;
        const uint32_t aC = aSm + cur * aBufB;
        const uint32_t bC = bSm + cur * bBufB;

        #pragma unroll
        for (int s = 0; s < 2; s++) {
            const uint32_t so = s * 32;
            uint32_t a[4][4];
            ldsm4(a[0], aC + aOff[0] + so);
            ldsm4(a[1], aC + aOff[1] + so);
            ldsm4(a[2], aC + aOff[2] + so);
            ldsm4(a[3], aC + aOff[3] + so);
            uint32_t bf[16];
            ldsm4(bf +  0, bC + bOff[0] + so);
            ldsm4(bf +  4, bC + bOff[1] + so);
            ldsm4(bf +  8, bC + bOff[2] + so);
            ldsm4(bf + 12, bC + bOff[3] + so);
            #pragma unroll
            for (int mt = 0; mt < 4; mt++)
                #pragma unroll
                for (int j = 0; j < 8; j++)
                    mma16(acc[mt][j], a[mt], bf[2 * j], bf[2 * j + 1]);
        }

        if (kt + 1 < KT) {
            sts(cur ^ 1);
            __syncthreads();
            if (kt + 2 < KT) ldg((kt + 2) * BK);
        }
    }

    // ---- epilogue
    #pragma unroll
    for (int mt = 0; mt < 4; mt++) {
        int row0 = m0 + wm * 64 + mt * 16 + d;
        #pragma unroll
        for (int j = 0; j < 8; j++) {
            int col = n0 + wn * 64 + j * 8 + 2 * c;
            float bx = 0.0f, by = 0.0f;
            if (bias) { bx = bias[col]; by = bias[col + 1]; }
            #pragma unroll
            for (int hrow = 0; hrow < 2; hrow++) {
                int rr = row0 + hrow * 8;
                size_t o = (size_t)rr * ldc + col;
                float vx = acc[mt][j][2 * hrow + 0] * scale + bx;
                float vy = acc[mt][j][2 * hrow + 1] * scale + by;
                if (residual) {
                    float2 rv = __half22float2(*(const __half2*)&residual[o]);
                    vx += rv.x; vy += rv.y;
                }
                if (OUTF16) {
                    *(__half2*)&((__half*)Cv + sC * zb)[o] = __floats2half2_rn(vx, vy);
                } else {
                    *(float2*)&((float*)Cv + sC * zb)[o] = make_float2(vx, vy);
                }
            }
        }
    }
}

// ---------------------------------------------------------------- softmax (fp16 in/out)
__global__ void softmax_causal_kernel() {
    int row = blockIdx.x;
    int s = row & (SEQ - 1);
    __half* p = g_attn + (size_t)row * SEQ;
    int L = s + 1;
    __shared__ float red[256];
    int tid = threadIdx.x;

    float m = -1e30f;
    for (int t = tid; t < L; t += 256) m = fmaxf(m, __half2float(p[t]));
    red[tid] = m; __syncthreads();
    #pragma unroll
    for (int o = 128; o > 0; o >>= 1) {
        if (tid < o) red[tid] = fmaxf(red[tid], red[tid + o]);
        __syncthreads();
    }
    m = red[0]; __syncthreads();

    float sum = 0.0f;
    for (int t = tid; t < L; t += 256) sum += __expf(__half2float(p[t]) - m);
    red[tid] = sum; __syncthreads();
    #pragma unroll
    for (int o = 128; o > 0; o >>= 1) {
        if (tid < o) red[tid] += red[tid + o];
        __syncthreads();
    }
    float inv = 1.0f / red[0];

    for (int t = tid; t < L; t += 256)
        p[t] = __float2half_rn(__expf(__half2float(p[t]) - m) * inv);
    for (int t = L + tid; t < SEQ; t += 256) p[t] = __float2half_rn(0.0f);
}

// ---------------------------------------------------------------- launch
extern "C" void kernel_launch(void* const* d_in, const int* in_sizes, int n_in,
                              void* d_out, int out_size) {
    const int*   x    = (const int*)  d_in[0];
    const float* emb  = (const float*)d_in[1];
    const float* pos  = (const float*)d_in[2];
    const float* Wk   = (const float*)d_in[3];
    const float* Wq   = (const float*)d_in[4];
    const float* Wv   = (const float*)d_in[5];
    const float* Wo   = (const float*)d_in[6];
    const float* bo   = (const float*)d_in[7];
    float* out = (float*)d_out;

    static __half *h = nullptr, *qkv, *attn, *z, *vT, *wT;
    if (!h) {
        cudaGetSymbolAddress((void**)&h,    g_h);
        cudaGetSymbolAddress((void**)&qkv,  g_qkv);
        cudaGetSymbolAddress((void**)&attn, g_attn);
        cudaGetSymbolAddress((void**)&z,    g_z);
        cudaGetSymbolAddress((void**)&vT,   g_vT);
        cudaGetSymbolAddress((void**)&wT,   g_wT);
        cudaFuncSetAttribute(hgemm<0>,
            cudaFuncAttributeMaxDynamicSharedMemorySize, SMEM_BYTES);
        cudaFuncSetAttribute(hgemm<1>,
            cudaFuncAttributeMaxDynamicSharedMemorySize, SMEM_BYTES);
    }
    const size_t SH = (size_t)SEQ * HID;
    const size_t SS = (size_t)SEQ * SEQ;
    const size_t HH = (size_t)HID * HID;

    __half* WqkvT = wT;
    __half* WoT   = wT + 3 * HH;

    __half* q = qkv;
    __half* k = qkv + HID;
    __half* v = qkv + 2 * HID;

    dim3 tb(32, 8);

    // L1: embedding
    embed_kernel<<<ROWS, 256>>>(x, emb, pos);

    // L2: Wq|Wk|Wv -> packed K-major fp16
    wT_qkv_kernel<<<dim3(HID / 32, HID / 32, 3), tb>>>(Wq, Wk, Wv, WqkvT);

    // L3: fused QKV gemm
    {
        dim3 grid(QKV_N / BN, ROWS / BM, 1);
        hgemm<1><<<grid, NTHREADS, SMEM_BYTES>>>(h, WqkvT, qkv, HID, HID, HID, QKV_N,
            nullptr, nullptr, 1.0f, 0, 0, 0, 0, 0, 0);
    }

    // L4 (captured): scores = q k^T / 32
    {
        dim3 grid(SEQ / BN, SEQ / BM, BATCH);
        hgemm<1><<<grid, NTHREADS, SMEM_BYTES>>>(q, k, attn, HID, QKV_N, QKV_N, SEQ,
            nullptr, nullptr, 1.0f / 32.0f, 1, 0,
            SEQ * (size_t)QKV_N, SEQ * (size_t)QKV_N, SS, 0);
    }

    // L5: softmax
    softmax_causal_kernel<<<ROWS, 256>>>();

    // L6: v^T per batch
    hT_kernel<<<dim3(HID / 32, SEQ / 32, BATCH), tb>>>(
        v, vT, SEQ, HID, QKV_N, SEQ * (size_t)QKV_N, SH);

    // L7: z = attn @ v + h
    {
        dim3 grid(HID / BN, SEQ / BM, BATCH);
        hgemm<1><<<grid, NTHREADS, SMEM_BYTES>>>(attn, vT, z, SEQ, SEQ, SEQ, HID,
            nullptr, h, 1.0f, 0, 1, SS, SH, SH, SH);
    }

    // L8: Wo -> K-major fp16
    wT_kernel<<<dim3(VOCAB_N / 32, HID / 32), tb>>>(Wo, WoT, HID, VOCAB_N);

    // L9: out = z @ Wo + bo (f32)
    {
        dim3 grid(VOCAB_N / BN, ROWS / BM, 1);
        hgemm<0><<<grid, NTHREADS, SMEM_BYTES>>>(z, WoT, out, HID, HID, HID, VOCAB_N,
            bo, nullptr, 1.0f, 0, 0, 0, 0, 0, 0);
    }
}